// round 9
// baseline (speedup 1.0000x reference)
#include <cuda_runtime.h>
#include <cuda_fp16.h>
#include <cstdint>

// Problem constants: B=8, C=128, H=W=64, O=128, 3x3, stride 1, pad 1, dil 1
#define BB 8
#define CC 128
#define HH 64
#define WW 64
#define OO 128
#define KTAP 9
#define HW (HH*WW)          // 4096
#define CK (CC*KTAP)        // 1152
#define NCHUNK 18           // CK / 64

// Scratch
__device__ __half g_xTh[BB*HH*WW*CC];            // [b][h][w][c] fp16, 8 MB
__device__ unsigned char g_wbH[NCHUNK*16384];    // fp16 B chunk tiles [ch][o(128)][c(64)]

// ---------------------------------------------------------------------------
// SMEM layout (dynamic), rows padded to 144 B for conflict-free ldmatrix
// ---------------------------------------------------------------------------
#define AROW 144
#define ATILE (128*AROW)            // 18432
#define A_OFF(st) ((st)*ATILE)
#define SM_B   (2*ATILE)            // 36864
#define B_OFF(st) (SM_B + (st)*ATILE)
#define SM_IDX (4*ATILE)            // 73728, [9][128][4] int
#define SM_WT  (SM_IDX + 9*128*4*4) // 92160, [9][128][4] float
#define SMEM_TOTAL (SM_WT + 9*128*4*4)  // 110592 -> 2 CTAs/SM

__device__ __forceinline__ uint32_t smem_u32(const void* p) {
    uint32_t a;
    asm("{ .reg .u64 t; cvta.to.shared.u64 t, %1; cvt.u32.u64 %0, t; }" : "=r"(a) : "l"(p));
    return a;
}
__device__ __forceinline__ void ldsm4(uint32_t addr, uint32_t* r) {
    asm volatile("ldmatrix.sync.aligned.m8n8.x4.shared.b16 {%0,%1,%2,%3}, [%4];"
                 : "=r"(r[0]), "=r"(r[1]), "=r"(r[2]), "=r"(r[3]) : "r"(addr));
}
// fp16-accumulate HMMA: D(f16x2 x2) = A*B + C
__device__ __forceinline__ void mma16816h(uint32_t* d, const uint32_t* a, const uint32_t* b,
                                          const uint32_t* c) {
    asm volatile("mma.sync.aligned.m16n8k16.row.col.f16.f16.f16.f16 "
                 "{%0,%1}, {%2,%3,%4,%5}, {%6,%7}, {%8,%9};"
                 : "=r"(d[0]), "=r"(d[1])
                 : "r"(a[0]), "r"(a[1]), "r"(a[2]), "r"(a[3]), "r"(b[0]), "r"(b[1]),
                   "r"(c[0]), "r"(c[1]));
}
__device__ __forceinline__ void cp16(uint32_t daddr, const void* src) {
    asm volatile("cp.async.cg.shared.global [%0], [%1], 16;" :: "r"(daddr), "l"(src));
}
#define CP_COMMIT() asm volatile("cp.async.commit_group;" ::: "memory")
#define CP_WAIT0()  asm volatile("cp.async.wait_group 0;" ::: "memory")

// ---------------------------------------------------------------------------
// Kernel 1: x [B,C,H,W] fp32 -> xTh [B,H,W,C] fp16
// ---------------------------------------------------------------------------
__global__ void xpose_kernel(const float* __restrict__ x) {
    __shared__ float tile[64][33];
    int b   = blockIdx.z;
    int hw0 = blockIdx.x * 32;
    int c0  = blockIdx.y * 64;
    const float* xb = x + (size_t)b * CC * HW;
#pragma unroll
    for (int j = 0; j < 64; j += 8)
        tile[threadIdx.y + j][threadIdx.x] =
            xb[(size_t)(c0 + threadIdx.y + j) * HW + hw0 + threadIdx.x];
    __syncthreads();
    __half* ob = g_xTh + (size_t)b * HW * CC + c0;
#pragma unroll
    for (int j = 0; j < 32; j += 8) {
        int row = threadIdx.y + j;
        __half2 h = __floats2half2_rn(tile[threadIdx.x * 2][row],
                                      tile[threadIdx.x * 2 + 1][row]);
        *reinterpret_cast<__half2*>(ob + (size_t)(hw0 + row) * CC + threadIdx.x * 2) = h;
    }
}

// ---------------------------------------------------------------------------
// Kernel 2: weight [O,C,3,3] -> per-chunk fp16 B tiles [ch][o(128)][c(64)]
// ---------------------------------------------------------------------------
__global__ void wprep_kernel(const float* __restrict__ w) {
    int idx = blockIdx.x * blockDim.x + threadIdx.x;
    if (idx >= NCHUNK * 128 * 64) return;
    int c  = idx & 63;
    int o  = (idx >> 6) & 127;
    int ch = idx >> 13;
    int k  = ch >> 1;
    int cf = ((ch & 1) << 6) + c;
    float v = w[(size_t)o * CK + cf * KTAP + k];
    *reinterpret_cast<__half*>(g_wbH + (size_t)ch * 16384 + o * 128 + c * 2) = __float2half(v);
}

// ---------------------------------------------------------------------------
// Kernel 3: fused gather + mma.sync fp16 GEMM (fp16-acc K=32 groups)
// grid = 256 (one CTA per 128 spatial positions of one batch), 256 threads
// ---------------------------------------------------------------------------
__global__ void __launch_bounds__(256, 2) dcn_mma_kernel(
    const float* __restrict__ offset,
    const float* __restrict__ bias,
    float* __restrict__ out)
{
    extern __shared__ char smem[];
    const uint32_t sb = smem_u32(smem);
    const int tid  = threadIdx.x;
    const int wid  = tid >> 5;
    const int lane = tid & 31;
    const int b    = blockIdx.x >> 5;
    const int ho0  = (blockIdx.x & 31) * 2;
    const int hw0  = (blockIdx.x & 31) * 128;

    int*   sIdx = reinterpret_cast<int*>(smem + SM_IDX);
    float* sWt  = reinterpret_cast<float*>(smem + SM_WT);

    // ---- precompute bilinear params for all (tap, m) ----
    for (int p = tid; p < KTAP * 128; p += 256) {
        int m = p & 127;
        int k = p >> 7;
        int ho = ho0 + (m >> 6), wo = m & 63;
        float dy = offset[(((size_t)b * 18 + 2 * k    ) * 64 + ho) * 64 + wo];
        float dx = offset[(((size_t)b * 18 + 2 * k + 1) * 64 + ho) * 64 + wo];
        float py = (float)(ho - 1 + k / 3) + dy;
        float px = (float)(wo - 1 + k % 3) + dx;
        float y0f = floorf(py), x0f = floorf(px);
        int   y0 = (int)y0f,    x0 = (int)x0f;
        float ly = py - y0f, lx = px - x0f;
        float w4[4] = { (1.f - ly) * (1.f - lx), (1.f - ly) * lx,
                        ly * (1.f - lx),         ly * lx };
#pragma unroll
        for (int i = 0; i < 4; i++) {
            int yy = y0 + (i >> 1);
            int xx = x0 + (i & 1);
            bool v = (yy >= 0) & (yy < HH) & (xx >= 0) & (xx < WW);
            sWt[p * 4 + i]  = v ? w4[i] : 0.f;
            sIdx[p * 4 + i] = v ? (((b * HH + yy) * WW + xx) * CC) : 0;
        }
    }
    __syncthreads();

    // ---- B tile cp.async ----
    auto cpasyncB = [&](int st, int ch) {
        const char* src = (const char*)g_wbH + (size_t)ch * 16384;
        uint32_t dB = sb + B_OFF(st);
#pragma unroll
        for (int i = 0; i < 4; i++) {
            int seg = tid + i * 256;
            int row = seg >> 3, s8 = seg & 7;
            cp16(dB + row * AROW + s8 * 16, src + seg * 16);
        }
    };

    // warp-coalesced fp16 bilinear gather
    const int sub4 = lane >> 3;
    const int l8   = lane & 7;
    auto gatherA = [&](int st, int ch) {
        const int k   = ch >> 1;
        const int cc  = ((ch & 1) << 6) + (l8 << 3);
        char* base = smem + A_OFF(st);
#pragma unroll
        for (int p = 0; p < 4; p++) {
            int m = (wid << 4) + (p << 2) + sub4;
            const int4   id = *reinterpret_cast<const int4*>(sIdx + ((k << 7) + m) * 4);
            const float4 wt = *reinterpret_cast<const float4*>(sWt + ((k << 7) + m) * 4);
            uint4 r0 = *reinterpret_cast<const uint4*>(g_xTh + id.x + cc);
            uint4 r1 = *reinterpret_cast<const uint4*>(g_xTh + id.y + cc);
            uint4 r2 = *reinterpret_cast<const uint4*>(g_xTh + id.z + cc);
            uint4 r3 = *reinterpret_cast<const uint4*>(g_xTh + id.w + cc);
            uint4 res;
            uint32_t* q0 = reinterpret_cast<uint32_t*>(&r0);
            uint32_t* q1 = reinterpret_cast<uint32_t*>(&r1);
            uint32_t* q2 = reinterpret_cast<uint32_t*>(&r2);
            uint32_t* q3 = reinterpret_cast<uint32_t*>(&r3);
            uint32_t* qr = reinterpret_cast<uint32_t*>(&res);
#pragma unroll
            for (int j = 0; j < 4; j++) {
                float2 f0 = __half22float2(*reinterpret_cast<__half2*>(&q0[j]));
                float2 f1 = __half22float2(*reinterpret_cast<__half2*>(&q1[j]));
                float2 f2 = __half22float2(*reinterpret_cast<__half2*>(&q2[j]));
                float2 f3 = __half22float2(*reinterpret_cast<__half2*>(&q3[j]));
                float vx = wt.x * f0.x + wt.y * f1.x + wt.z * f2.x + wt.w * f3.x;
                float vy = wt.x * f0.y + wt.y * f1.y + wt.z * f2.y + wt.w * f3.y;
                __half2 h = __floats2half2_rn(vx, vy);
                qr[j] = *reinterpret_cast<uint32_t*>(&h);
            }
            *reinterpret_cast<uint4*>(base + m * AROW + (l8 << 4)) = res;
        }
    };

    const int mbase = (wid >> 1) * 32;
    const int n0    = (wid & 1) * 64;

    float acc[2][8][4];
#pragma unroll
    for (int i = 0; i < 2; i++)
#pragma unroll
        for (int j = 0; j < 8; j++)
#pragma unroll
            for (int q = 0; q < 4; q++) acc[i][j][q] = 0.f;

    uint32_t a16[2][8][2];          // fp16 group accumulators
    const uint32_t zz[2] = {0u, 0u};

    auto mma_chunk = [&](int st) {
        const uint32_t aT = sb + A_OFF(st);
        const uint32_t bT = sb + B_OFF(st);
        const uint32_t aoff = (uint32_t)(lane & 15) * AROW + ((uint32_t)(lane >> 4) << 4);
        const uint32_t boff = (uint32_t)(n0 + ((lane >> 4) << 3) + (lane & 7)) * AROW
                            + (((uint32_t)(lane >> 3) & 1) << 4);
#pragma unroll
        for (int s = 0; s < 4; s++) {
            const bool fresh   = (s & 1) == 0;   // start of K=32 group
            const bool promote = (s & 1) == 1;   // end of K=32 group
            uint32_t Ah[2][4];
#pragma unroll
            for (int mt = 0; mt < 2; mt++)
                ldsm4(aT + aoff + (mbase + mt * 16) * AROW + s * 32, Ah[mt]);
#pragma unroll
            for (int p = 0; p < 4; p++) {
                uint32_t Bf[4];
                ldsm4(bT + boff + p * 16 * AROW + s * 32, Bf);
#pragma unroll
                for (int mt = 0; mt < 2; mt++) {
                    mma16816h(a16[mt][p * 2],     Ah[mt], &Bf[0],
                              fresh ? zz : a16[mt][p * 2]);
                    mma16816h(a16[mt][p * 2 + 1], Ah[mt], &Bf[2],
                              fresh ? zz : a16[mt][p * 2 + 1]);
                }
            }
            if (promote) {
#pragma unroll
                for (int mt = 0; mt < 2; mt++)
#pragma unroll
                    for (int nt = 0; nt < 8; nt++) {
                        float2 lo = __half22float2(
                            *reinterpret_cast<__half2*>(&a16[mt][nt][0]));
                        float2 hi = __half22float2(
                            *reinterpret_cast<__half2*>(&a16[mt][nt][1]));
                        acc[mt][nt][0] += lo.x;
                        acc[mt][nt][1] += lo.y;
                        acc[mt][nt][2] += hi.x;
                        acc[mt][nt][3] += hi.y;
                    }
            }
        }
    };

    // ---- prologue: fill stage 0 ----
    cpasyncB(0, 0);
    CP_COMMIT();
    gatherA(0, 0);
    CP_WAIT0();
    __syncthreads();

    // ---- main loop, double-buffered; SMSP-partner warps alternate order ----
    const bool gfirst = (wid >> 2) & 1;
    for (int ch = 0; ch < NCHUNK; ch++) {
        int cur = ch & 1, nxt = cur ^ 1;
        if (ch + 1 < NCHUNK) { cpasyncB(nxt, ch + 1); CP_COMMIT(); }
        if (gfirst) {
            if (ch + 1 < NCHUNK) gatherA(nxt, ch + 1);
            mma_chunk(cur);
        } else {
            mma_chunk(cur);
            if (ch + 1 < NCHUNK) gatherA(nxt, ch + 1);
        }
        CP_WAIT0();
        __syncthreads();
    }

    // ---- epilogue: write 32x64 per warp, add bias ----
#pragma unroll
    for (int nt = 0; nt < 8; nt++) {
        int n = n0 + nt * 8 + (lane & 3) * 2;
        float bv0 = __ldg(bias + n);
        float bv1 = __ldg(bias + n + 1);
        float* o0 = out + ((size_t)b * OO + n) * HW + hw0;
        float* o1 = o0 + HW;
#pragma unroll
        for (int mt = 0; mt < 2; mt++) {
            int mr = mbase + mt * 16 + (lane >> 2);
            o0[mr]     = acc[mt][nt][0] + bv0;
            o1[mr]     = acc[mt][nt][1] + bv1;
            o0[mr + 8] = acc[mt][nt][2] + bv0;
            o1[mr + 8] = acc[mt][nt][3] + bv1;
        }
    }
}

// ---------------------------------------------------------------------------
extern "C" void kernel_launch(void* const* d_in, const int* in_sizes, int n_in,
                              void* d_out, int out_size)
{
    const float* x      = (const float*)d_in[0];
    const float* offset = (const float*)d_in[1];
    const float* weight = (const float*)d_in[2];
    const float* bias   = (const float*)d_in[3];
    float* out = (float*)d_out;

    cudaFuncSetAttribute(dcn_mma_kernel,
                         cudaFuncAttributeMaxDynamicSharedMemorySize, SMEM_TOTAL);

    dim3 g1(HW / 32, CC / 64, BB), b1(32, 8);
    xpose_kernel<<<g1, b1>>>(x);

    int nw = NCHUNK * 128 * 64;
    wprep_kernel<<<(nw + 255) / 256, 256>>>(weight);

    dcn_mma_kernel<<<256, 256, SMEM_TOTAL>>>(offset, bias, out);
}

// round 10
// speedup vs baseline: 1.2246x; 1.2246x over previous
#include <cuda_runtime.h>
#include <cuda_fp16.h>
#include <cstdint>

// Problem constants: B=8, C=128, H=W=64, O=128, 3x3, stride 1, pad 1, dil 1
#define BB 8
#define CC 128
#define HH 64
#define WW 64
#define OO 128
#define KTAP 9
#define HW (HH*WW)          // 4096
#define CK (CC*KTAP)        // 1152
#define NCHUNK 18           // CK / 64

// Scratch
__device__ __half g_xTh[BB*HH*WW*CC];            // [b][h][w][c] fp16, 8 MB
__device__ unsigned char g_wbH[NCHUNK*16384];    // fp16 B chunk tiles [ch][o(128)][c(64)]

// ---------------------------------------------------------------------------
// SMEM layout (dynamic), rows padded to 144 B for conflict-free ldmatrix
// ---------------------------------------------------------------------------
#define AROW 144
#define ATILE (128*AROW)            // 18432
#define A_OFF(st) ((st)*ATILE)
#define SM_B   (2*ATILE)            // 36864
#define B_OFF(st) (SM_B + (st)*ATILE)
#define SM_IDX (4*ATILE)            // 73728, [9][128][4] int
#define SM_WT  (SM_IDX + 9*128*4*4) // 92160, [9][128][4] float
#define SMEM_TOTAL (SM_WT + 9*128*4*4)  // 110592 -> 2 CTAs/SM

__device__ __forceinline__ uint32_t smem_u32(const void* p) {
    uint32_t a;
    asm("{ .reg .u64 t; cvta.to.shared.u64 t, %1; cvt.u32.u64 %0, t; }" : "=r"(a) : "l"(p));
    return a;
}
__device__ __forceinline__ void ldsm4(uint32_t addr, uint32_t* r) {
    asm volatile("ldmatrix.sync.aligned.m8n8.x4.shared.b16 {%0,%1,%2,%3}, [%4];"
                 : "=r"(r[0]), "=r"(r[1]), "=r"(r[2]), "=r"(r[3]) : "r"(addr));
}
__device__ __forceinline__ void mma16816(float* d, const uint32_t* a, const uint32_t* b) {
    asm volatile("mma.sync.aligned.m16n8k16.row.col.f32.f16.f16.f32 "
                 "{%0,%1,%2,%3}, {%4,%5,%6,%7}, {%8,%9}, {%0,%1,%2,%3};"
                 : "+f"(d[0]), "+f"(d[1]), "+f"(d[2]), "+f"(d[3])
                 : "r"(a[0]), "r"(a[1]), "r"(a[2]), "r"(a[3]), "r"(b[0]), "r"(b[1]));
}
__device__ __forceinline__ void cp16(uint32_t daddr, const void* src) {
    asm volatile("cp.async.cg.shared.global [%0], [%1], 16;" :: "r"(daddr), "l"(src));
}
#define CP_COMMIT() asm volatile("cp.async.commit_group;" ::: "memory")
#define CP_WAIT0()  asm volatile("cp.async.wait_group 0;" ::: "memory")

// ---------------------------------------------------------------------------
// Kernel 1: x [B,C,H,W] fp32 -> xTh [B,H,W,C] fp16
// 128hw x 64c tiles, float4 reads, coalesced half2x2 writes
// grid (32, 2, B), block 256
// ---------------------------------------------------------------------------
__global__ void __launch_bounds__(256) xpose_kernel(const float* __restrict__ x) {
    __shared__ float tile[64][129];
    const int b   = blockIdx.z;
    const int hw0 = blockIdx.x * 128;
    const int c0  = blockIdx.y * 64;
    const int t   = threadIdx.x;
    const float* xb = x + (size_t)b * CC * HW;

    // read: 64 rows (c) x 128 cols (hw), float4 per thread
#pragma unroll
    for (int j = 0; j < 64; j += 8) {
        int c = j + (t >> 5);
        float4 v = *reinterpret_cast<const float4*>(
            &xb[(size_t)(c0 + c) * HW + hw0 + (t & 31) * 4]);
        tile[c][(t & 31) * 4 + 0] = v.x;
        tile[c][(t & 31) * 4 + 1] = v.y;
        tile[c][(t & 31) * 4 + 2] = v.z;
        tile[c][(t & 31) * 4 + 3] = v.w;
    }
    __syncthreads();

    // write: 128 rows (hw) x 64 ch, 4 ch per thread packed to half2x2 (8B)
    __half* ob = g_xTh + (size_t)b * HW * CC + c0;
    const int ch4 = (t & 15) * 4;
#pragma unroll
    for (int j = 0; j < 128; j += 16) {
        int hw = j + (t >> 4);
        __half2 h0 = __floats2half2_rn(tile[ch4][hw],     tile[ch4 + 1][hw]);
        __half2 h1 = __floats2half2_rn(tile[ch4 + 2][hw], tile[ch4 + 3][hw]);
        uint2 v = make_uint2(*reinterpret_cast<uint32_t*>(&h0),
                             *reinterpret_cast<uint32_t*>(&h1));
        *reinterpret_cast<uint2*>(ob + (size_t)(hw0 + hw) * CC + ch4) = v;
    }
}

// ---------------------------------------------------------------------------
// Kernel 2: weight [O,C,3,3] -> per-chunk fp16 B tiles [ch][o(128)][c(64)]
// ---------------------------------------------------------------------------
__global__ void wprep_kernel(const float* __restrict__ w) {
    int idx = blockIdx.x * blockDim.x + threadIdx.x;
    if (idx >= NCHUNK * 128 * 64) return;
    int c  = idx & 63;
    int o  = (idx >> 6) & 127;
    int ch = idx >> 13;
    int k  = ch >> 1;
    int cf = ((ch & 1) << 6) + c;
    float v = w[(size_t)o * CK + cf * KTAP + k];
    *reinterpret_cast<__half*>(g_wbH + (size_t)ch * 16384 + o * 128 + c * 2) = __float2half(v);
}

// ---------------------------------------------------------------------------
// Kernel 3: fused gather + mma.sync fp16 GEMM (fp32 accum) — R8 configuration
// grid = 256 (one CTA per 128 spatial positions of one batch), 256 threads
// ---------------------------------------------------------------------------
__global__ void __launch_bounds__(256, 2) dcn_mma_kernel(
    const float* __restrict__ offset,
    const float* __restrict__ bias,
    float* __restrict__ out)
{
    extern __shared__ char smem[];
    const uint32_t sb = smem_u32(smem);
    const int tid  = threadIdx.x;
    const int wid  = tid >> 5;
    const int lane = tid & 31;
    const int b    = blockIdx.x >> 5;
    const int ho0  = (blockIdx.x & 31) * 2;
    const int hw0  = (blockIdx.x & 31) * 128;

    int*   sIdx = reinterpret_cast<int*>(smem + SM_IDX);
    float* sWt  = reinterpret_cast<float*>(smem + SM_WT);

    // ---- precompute bilinear params for all (tap, m) ----
    for (int p = tid; p < KTAP * 128; p += 256) {
        int m = p & 127;
        int k = p >> 7;
        int ho = ho0 + (m >> 6), wo = m & 63;
        float dy = offset[(((size_t)b * 18 + 2 * k    ) * 64 + ho) * 64 + wo];
        float dx = offset[(((size_t)b * 18 + 2 * k + 1) * 64 + ho) * 64 + wo];
        float py = (float)(ho - 1 + k / 3) + dy;
        float px = (float)(wo - 1 + k % 3) + dx;
        float y0f = floorf(py), x0f = floorf(px);
        int   y0 = (int)y0f,    x0 = (int)x0f;
        float ly = py - y0f, lx = px - x0f;
        float w4[4] = { (1.f - ly) * (1.f - lx), (1.f - ly) * lx,
                        ly * (1.f - lx),         ly * lx };
#pragma unroll
        for (int i = 0; i < 4; i++) {
            int yy = y0 + (i >> 1);
            int xx = x0 + (i & 1);
            bool v = (yy >= 0) & (yy < HH) & (xx >= 0) & (xx < WW);
            sWt[p * 4 + i]  = v ? w4[i] : 0.f;
            sIdx[p * 4 + i] = v ? (((b * HH + yy) * WW + xx) * CC) : 0;
        }
    }
    __syncthreads();

    // ---- B tile cp.async ----
    auto cpasyncB = [&](int st, int ch) {
        const char* src = (const char*)g_wbH + (size_t)ch * 16384;
        uint32_t dB = sb + B_OFF(st);
#pragma unroll
        for (int i = 0; i < 4; i++) {
            int seg = tid + i * 256;
            int row = seg >> 3, s8 = seg & 7;
            cp16(dB + row * AROW + s8 * 16, src + seg * 16);
        }
    };

    // warp-coalesced fp16 bilinear gather
    const int sub4 = lane >> 3;
    const int l8   = lane & 7;
    auto gatherA = [&](int st, int ch) {
        const int k   = ch >> 1;
        const int cc  = ((ch & 1) << 6) + (l8 << 3);
        char* base = smem + A_OFF(st);
#pragma unroll
        for (int p = 0; p < 4; p++) {
            int m = (wid << 4) + (p << 2) + sub4;
            const int4   id = *reinterpret_cast<const int4*>(sIdx + ((k << 7) + m) * 4);
            const float4 wt = *reinterpret_cast<const float4*>(sWt + ((k << 7) + m) * 4);
            uint4 r0 = *reinterpret_cast<const uint4*>(g_xTh + id.x + cc);
            uint4 r1 = *reinterpret_cast<const uint4*>(g_xTh + id.y + cc);
            uint4 r2 = *reinterpret_cast<const uint4*>(g_xTh + id.z + cc);
            uint4 r3 = *reinterpret_cast<const uint4*>(g_xTh + id.w + cc);
            uint4 res;
            uint32_t* q0 = reinterpret_cast<uint32_t*>(&r0);
            uint32_t* q1 = reinterpret_cast<uint32_t*>(&r1);
            uint32_t* q2 = reinterpret_cast<uint32_t*>(&r2);
            uint32_t* q3 = reinterpret_cast<uint32_t*>(&r3);
            uint32_t* qr = reinterpret_cast<uint32_t*>(&res);
#pragma unroll
            for (int j = 0; j < 4; j++) {
                float2 f0 = __half22float2(*reinterpret_cast<__half2*>(&q0[j]));
                float2 f1 = __half22float2(*reinterpret_cast<__half2*>(&q1[j]));
                float2 f2 = __half22float2(*reinterpret_cast<__half2*>(&q2[j]));
                float2 f3 = __half22float2(*reinterpret_cast<__half2*>(&q3[j]));
                float vx = wt.x * f0.x + wt.y * f1.x + wt.z * f2.x + wt.w * f3.x;
                float vy = wt.x * f0.y + wt.y * f1.y + wt.z * f2.y + wt.w * f3.y;
                __half2 h = __floats2half2_rn(vx, vy);
                qr[j] = *reinterpret_cast<uint32_t*>(&h);
            }
            *reinterpret_cast<uint4*>(base + m * AROW + (l8 << 4)) = res;
        }
    };

    const int mbase = (wid >> 1) * 32;
    const int n0    = (wid & 1) * 64;
    float acc[2][8][4];
#pragma unroll
    for (int i = 0; i < 2; i++)
#pragma unroll
        for (int j = 0; j < 8; j++)
#pragma unroll
            for (int q = 0; q < 4; q++) acc[i][j][q] = 0.f;

    auto mma_chunk = [&](int st) {
        const uint32_t aT = sb + A_OFF(st);
        const uint32_t bT = sb + B_OFF(st);
        const uint32_t aoff = (uint32_t)(lane & 15) * AROW + ((uint32_t)(lane >> 4) << 4);
        const uint32_t boff = (uint32_t)(n0 + ((lane >> 4) << 3) + (lane & 7)) * AROW
                            + (((uint32_t)(lane >> 3) & 1) << 4);
#pragma unroll
        for (int s = 0; s < 4; s++) {
            uint32_t Ah[2][4];
#pragma unroll
            for (int mt = 0; mt < 2; mt++)
                ldsm4(aT + aoff + (mbase + mt * 16) * AROW + s * 32, Ah[mt]);
#pragma unroll
            for (int p = 0; p < 4; p++) {
                uint32_t Bf[4];
                ldsm4(bT + boff + p * 16 * AROW + s * 32, Bf);
#pragma unroll
                for (int mt = 0; mt < 2; mt++) {
                    mma16816(acc[mt][p * 2],     Ah[mt], &Bf[0]);
                    mma16816(acc[mt][p * 2 + 1], Ah[mt], &Bf[2]);
                }
            }
        }
    };

    // ---- prologue: fill stage 0 ----
    cpasyncB(0, 0);
    CP_COMMIT();
    gatherA(0, 0);
    CP_WAIT0();
    __syncthreads();

    // ---- main loop, double-buffered; SMSP-partner warps alternate order ----
    const bool gfirst = (wid >> 2) & 1;
    for (int ch = 0; ch < NCHUNK; ch++) {
        int cur = ch & 1, nxt = cur ^ 1;
        if (ch + 1 < NCHUNK) { cpasyncB(nxt, ch + 1); CP_COMMIT(); }
        if (gfirst) {
            if (ch + 1 < NCHUNK) gatherA(nxt, ch + 1);
            mma_chunk(cur);
        } else {
            mma_chunk(cur);
            if (ch + 1 < NCHUNK) gatherA(nxt, ch + 1);
        }
        CP_WAIT0();
        __syncthreads();
    }

    // ---- epilogue: write 32x64 per warp, add bias ----
#pragma unroll
    for (int nt = 0; nt < 8; nt++) {
        int n = n0 + nt * 8 + (lane & 3) * 2;
        float bv0 = __ldg(bias + n);
        float bv1 = __ldg(bias + n + 1);
        float* o0 = out + ((size_t)b * OO + n) * HW + hw0;
        float* o1 = o0 + HW;
#pragma unroll
        for (int mt = 0; mt < 2; mt++) {
            int mr = mbase + mt * 16 + (lane >> 2);
            o0[mr]     = acc[mt][nt][0] + bv0;
            o1[mr]     = acc[mt][nt][1] + bv1;
            o0[mr + 8] = acc[mt][nt][2] + bv0;
            o1[mr + 8] = acc[mt][nt][3] + bv1;
        }
    }
}

// ---------------------------------------------------------------------------
extern "C" void kernel_launch(void* const* d_in, const int* in_sizes, int n_in,
                              void* d_out, int out_size)
{
    const float* x      = (const float*)d_in[0];
    const float* offset = (const float*)d_in[1];
    const float* weight = (const float*)d_in[2];
    const float* bias   = (const float*)d_in[3];
    float* out = (float*)d_out;

    cudaFuncSetAttribute(dcn_mma_kernel,
                         cudaFuncAttributeMaxDynamicSharedMemorySize, SMEM_TOTAL);

    dim3 g1(HW / 128, CC / 64, BB), b1(256);
    xpose_kernel<<<g1, b1>>>(x);

    int nw = NCHUNK * 128 * 64;
    wprep_kernel<<<(nw + 255) / 256, 256>>>(weight);

    dcn_mma_kernel<<<256, 256, SMEM_TOTAL>>>(offset, bias, out);
}

// round 11
// speedup vs baseline: 1.2837x; 1.0482x over previous
#include <cuda_runtime.h>
#include <cuda_fp16.h>
#include <cstdint>

// Problem constants: B=8, C=128, H=W=64, O=128, 3x3, stride 1, pad 1, dil 1
#define BB 8
#define CC 128
#define HH 64
#define WW 64
#define OO 128
#define KTAP 9
#define HW (HH*WW)          // 4096
#define CK (CC*KTAP)        // 1152
#define NCHUNK 18           // CK / 64

// Scratch
__device__ __half g_xTh[BB*HH*WW*CC];            // [b][h][w][c] fp16, 8 MB
__device__ unsigned char g_wbH[NCHUNK*16384];    // fp16 B chunk tiles [ch][o(128)][c(64)]

// ---------------------------------------------------------------------------
// SMEM layout (dynamic), rows padded to 144 B for conflict-free ldmatrix
// ---------------------------------------------------------------------------
#define AROW 144
#define ATILE (128*AROW)            // 18432
#define A_OFF(st) ((st)*ATILE)
#define SM_B   (2*ATILE)            // 36864
#define B_OFF(st) (SM_B + (st)*ATILE)
#define SM_IDX (4*ATILE)            // 73728, [9][128][4] int
#define SM_WT  (SM_IDX + 9*128*4*4) // 92160, [9][128][4] float
#define SMEM_TOTAL (SM_WT + 9*128*4*4)  // 110592 -> 2 CTAs/SM
#define EROW 132                    // epilogue smem row pitch (floats)

__device__ __forceinline__ uint32_t smem_u32(const void* p) {
    uint32_t a;
    asm("{ .reg .u64 t; cvta.to.shared.u64 t, %1; cvt.u32.u64 %0, t; }" : "=r"(a) : "l"(p));
    return a;
}
__device__ __forceinline__ void ldsm4(uint32_t addr, uint32_t* r) {
    asm volatile("ldmatrix.sync.aligned.m8n8.x4.shared.b16 {%0,%1,%2,%3}, [%4];"
                 : "=r"(r[0]), "=r"(r[1]), "=r"(r[2]), "=r"(r[3]) : "r"(addr));
}
__device__ __forceinline__ void mma16816(float* d, const uint32_t* a, const uint32_t* b) {
    asm volatile("mma.sync.aligned.m16n8k16.row.col.f32.f16.f16.f32 "
                 "{%0,%1,%2,%3}, {%4,%5,%6,%7}, {%8,%9}, {%0,%1,%2,%3};"
                 : "+f"(d[0]), "+f"(d[1]), "+f"(d[2]), "+f"(d[3])
                 : "r"(a[0]), "r"(a[1]), "r"(a[2]), "r"(a[3]), "r"(b[0]), "r"(b[1]));
}
__device__ __forceinline__ void cp16(uint32_t daddr, const void* src) {
    asm volatile("cp.async.cg.shared.global [%0], [%1], 16;" :: "r"(daddr), "l"(src));
}
#define CP_COMMIT() asm volatile("cp.async.commit_group;" ::: "memory")
#define CP_WAIT0()  asm volatile("cp.async.wait_group 0;" ::: "memory")

// ---------------------------------------------------------------------------
// Kernel 1 (fused prep): blockIdx.x < 128 -> xpose tile; else -> wprep slice
// grid (128+36, 2, 8), block (32,8)
// ---------------------------------------------------------------------------
__global__ void prep_kernel(const float* __restrict__ x, const float* __restrict__ w) {
    if (blockIdx.x < 128) {
        // x [B,C,H,W] fp32 -> xTh [B,H,W,C] fp16 (64c x 32hw tile)
        __shared__ float tile[64][33];
        int b   = blockIdx.z;
        int hw0 = blockIdx.x * 32;
        int c0  = blockIdx.y * 64;
        const float* xb = x + (size_t)b * CC * HW;
#pragma unroll
        for (int j = 0; j < 64; j += 8)
            tile[threadIdx.y + j][threadIdx.x] =
                xb[(size_t)(c0 + threadIdx.y + j) * HW + hw0 + threadIdx.x];
        __syncthreads();
        __half* ob = g_xTh + (size_t)b * HW * CC + c0;
#pragma unroll
        for (int j = 0; j < 32; j += 8) {
            int row = threadIdx.y + j;
            __half2 h = __floats2half2_rn(tile[threadIdx.x * 2][row],
                                          tile[threadIdx.x * 2 + 1][row]);
            *reinterpret_cast<__half2*>(ob + (size_t)(hw0 + row) * CC + threadIdx.x * 2) = h;
        }
    } else {
        // weight [O,C,3,3] -> per-chunk fp16 B tiles [ch][o(128)][c(64)]
        int slice = (blockIdx.x - 128) * 16 + blockIdx.z * 2 + blockIdx.y;  // 0..575
        int idx = slice * 256 + threadIdx.y * 32 + threadIdx.x;
        if (idx >= NCHUNK * 128 * 64) return;
        int c  = idx & 63;
        int o  = (idx >> 6) & 127;
        int ch = idx >> 13;
        int k  = ch >> 1;
        int cf = ((ch & 1) << 6) + c;
        float v = w[(size_t)o * CK + cf * KTAP + k];
        *reinterpret_cast<__half*>(g_wbH + (size_t)ch * 16384 + o * 128 + c * 2) =
            __float2half(v);
    }
}

// ---------------------------------------------------------------------------
// Kernel 2: fused gather + mma.sync fp16 GEMM (fp32 accum)
// grid = 256 (one CTA per 128 spatial positions of one batch), 256 threads
// ---------------------------------------------------------------------------
__global__ void __launch_bounds__(256, 2) dcn_mma_kernel(
    const float* __restrict__ offset,
    const float* __restrict__ bias,
    float* __restrict__ out)
{
    extern __shared__ char smem[];
    const uint32_t sb = smem_u32(smem);
    const int tid  = threadIdx.x;
    const int wid  = tid >> 5;
    const int lane = tid & 31;
    const int b    = blockIdx.x >> 5;
    const int ho0  = (blockIdx.x & 31) * 2;
    const int hw0  = (blockIdx.x & 31) * 128;

    int*   sIdx = reinterpret_cast<int*>(smem + SM_IDX);
    float* sWt  = reinterpret_cast<float*>(smem + SM_WT);

    // ---- precompute bilinear params for all (tap, m) ----
    for (int p = tid; p < KTAP * 128; p += 256) {
        int m = p & 127;
        int k = p >> 7;
        int ho = ho0 + (m >> 6), wo = m & 63;
        float dy = offset[(((size_t)b * 18 + 2 * k    ) * 64 + ho) * 64 + wo];
        float dx = offset[(((size_t)b * 18 + 2 * k + 1) * 64 + ho) * 64 + wo];
        float py = (float)(ho - 1 + k / 3) + dy;
        float px = (float)(wo - 1 + k % 3) + dx;
        float y0f = floorf(py), x0f = floorf(px);
        int   y0 = (int)y0f,    x0 = (int)x0f;
        float ly = py - y0f, lx = px - x0f;
        float w4[4] = { (1.f - ly) * (1.f - lx), (1.f - ly) * lx,
                        ly * (1.f - lx),         ly * lx };
#pragma unroll
        for (int i = 0; i < 4; i++) {
            int yy = y0 + (i >> 1);
            int xx = x0 + (i & 1);
            bool v = (yy >= 0) & (yy < HH) & (xx >= 0) & (xx < WW);
            sWt[p * 4 + i]  = v ? w4[i] : 0.f;
            sIdx[p * 4 + i] = v ? (((b * HH + yy) * WW + xx) * CC) : 0;
        }
    }
    __syncthreads();

    // ---- B tile cp.async ----
    auto cpasyncB = [&](int st, int ch) {
        const char* src = (const char*)g_wbH + (size_t)ch * 16384;
        uint32_t dB = sb + B_OFF(st);
#pragma unroll
        for (int i = 0; i < 4; i++) {
            int seg = tid + i * 256;
            int row = seg >> 3, s8 = seg & 7;
            cp16(dB + row * AROW + s8 * 16, src + seg * 16);
        }
    };

    // warp-coalesced fp16 bilinear gather
    const int sub4 = lane >> 3;
    const int l8   = lane & 7;
    auto gatherA = [&](int st, int ch) {
        const int k   = ch >> 1;
        const int cc  = ((ch & 1) << 6) + (l8 << 3);
        char* base = smem + A_OFF(st);
#pragma unroll
        for (int p = 0; p < 4; p++) {
            int m = (wid << 4) + (p << 2) + sub4;
            const int4   id = *reinterpret_cast<const int4*>(sIdx + ((k << 7) + m) * 4);
            const float4 wt = *reinterpret_cast<const float4*>(sWt + ((k << 7) + m) * 4);
            uint4 r0 = *reinterpret_cast<const uint4*>(g_xTh + id.x + cc);
            uint4 r1 = *reinterpret_cast<const uint4*>(g_xTh + id.y + cc);
            uint4 r2 = *reinterpret_cast<const uint4*>(g_xTh + id.z + cc);
            uint4 r3 = *reinterpret_cast<const uint4*>(g_xTh + id.w + cc);
            uint4 res;
            uint32_t* q0 = reinterpret_cast<uint32_t*>(&r0);
            uint32_t* q1 = reinterpret_cast<uint32_t*>(&r1);
            uint32_t* q2 = reinterpret_cast<uint32_t*>(&r2);
            uint32_t* q3 = reinterpret_cast<uint32_t*>(&r3);
            uint32_t* qr = reinterpret_cast<uint32_t*>(&res);
#pragma unroll
            for (int j = 0; j < 4; j++) {
                float2 f0 = __half22float2(*reinterpret_cast<__half2*>(&q0[j]));
                float2 f1 = __half22float2(*reinterpret_cast<__half2*>(&q1[j]));
                float2 f2 = __half22float2(*reinterpret_cast<__half2*>(&q2[j]));
                float2 f3 = __half22float2(*reinterpret_cast<__half2*>(&q3[j]));
                float vx = wt.x * f0.x + wt.y * f1.x + wt.z * f2.x + wt.w * f3.x;
                float vy = wt.x * f0.y + wt.y * f1.y + wt.z * f2.y + wt.w * f3.y;
                __half2 h = __floats2half2_rn(vx, vy);
                qr[j] = *reinterpret_cast<uint32_t*>(&h);
            }
            *reinterpret_cast<uint4*>(base + m * AROW + (l8 << 4)) = res;
        }
    };

    const int mbase = (wid >> 1) * 32;
    const int n0    = (wid & 1) * 64;
    float acc[2][8][4];
#pragma unroll
    for (int i = 0; i < 2; i++)
#pragma unroll
        for (int j = 0; j < 8; j++)
#pragma unroll
            for (int q = 0; q < 4; q++) acc[i][j][q] = 0.f;

    auto mma_chunk = [&](int st) {
        const uint32_t aT = sb + A_OFF(st);
        const uint32_t bT = sb + B_OFF(st);
        const uint32_t aoff = (uint32_t)(lane & 15) * AROW + ((uint32_t)(lane >> 4) << 4);
        const uint32_t boff = (uint32_t)(n0 + ((lane >> 4) << 3) + (lane & 7)) * AROW
                            + (((uint32_t)(lane >> 3) & 1) << 4);
#pragma unroll
        for (int s = 0; s < 4; s++) {
            uint32_t Ah[2][4];
#pragma unroll
            for (int mt = 0; mt < 2; mt++)
                ldsm4(aT + aoff + (mbase + mt * 16) * AROW + s * 32, Ah[mt]);
#pragma unroll
            for (int p = 0; p < 4; p++) {
                uint32_t Bf[4];
                ldsm4(bT + boff + p * 16 * AROW + s * 32, Bf);
#pragma unroll
                for (int mt = 0; mt < 2; mt++) {
                    mma16816(acc[mt][p * 2],     Ah[mt], &Bf[0]);
                    mma16816(acc[mt][p * 2 + 1], Ah[mt], &Bf[2]);
                }
            }
        }
    };

    // ---- prologue: fill stage 0 ----
    cpasyncB(0, 0);
    CP_COMMIT();
    gatherA(0, 0);
    CP_WAIT0();
    __syncthreads();

    // ---- main loop, double-buffered; SMSP-partner warps alternate order ----
    const bool gfirst = (wid >> 2) & 1;
    for (int ch = 0; ch < NCHUNK; ch++) {
        int cur = ch & 1, nxt = cur ^ 1;
        if (ch + 1 < NCHUNK) { cpasyncB(nxt, ch + 1); CP_COMMIT(); }
        if (gfirst) {
            if (ch + 1 < NCHUNK) gatherA(nxt, ch + 1);
            mma_chunk(cur);
        } else {
            mma_chunk(cur);
            if (ch + 1 < NCHUNK) gatherA(nxt, ch + 1);
        }
        CP_WAIT0();
        __syncthreads();
    }

    // ---- epilogue: stage tile in smem (reuse A/B region), coalesced stores ----
    float* etile = reinterpret_cast<float*>(smem);  // [128 n][EROW] floats
#pragma unroll
    for (int nt = 0; nt < 8; nt++) {
        int n = n0 + nt * 8 + (lane & 3) * 2;
        float bv0 = __ldg(bias + n);
        float bv1 = __ldg(bias + n + 1);
#pragma unroll
        for (int mt = 0; mt < 2; mt++) {
            int mr = mbase + mt * 16 + (lane >> 2);
            etile[n * EROW + mr]           = acc[mt][nt][0] + bv0;
            etile[(n + 1) * EROW + mr]     = acc[mt][nt][1] + bv1;
            etile[n * EROW + mr + 8]       = acc[mt][nt][2] + bv0;
            etile[(n + 1) * EROW + mr + 8] = acc[mt][nt][3] + bv1;
        }
    }
    __syncthreads();
    {
        const int m4 = (tid & 31) * 4;
        const int nb = tid >> 5;
        float* ob = out + (size_t)b * OO * HW + hw0;
#pragma unroll
        for (int i = 0; i < 16; i++) {
            int n = i * 8 + nb;
            float4 v = *reinterpret_cast<const float4*>(etile + n * EROW + m4);
            *reinterpret_cast<float4*>(ob + (size_t)n * HW + m4) = v;
        }
    }
}

// ---------------------------------------------------------------------------
extern "C" void kernel_launch(void* const* d_in, const int* in_sizes, int n_in,
                              void* d_out, int out_size)
{
    const float* x      = (const float*)d_in[0];
    const float* offset = (const float*)d_in[1];
    const float* weight = (const float*)d_in[2];
    const float* bias   = (const float*)d_in[3];
    float* out = (float*)d_out;

    cudaFuncSetAttribute(dcn_mma_kernel,
                         cudaFuncAttributeMaxDynamicSharedMemorySize, SMEM_TOTAL);

    dim3 g1(128 + 36, 2, BB), b1(32, 8);
    prep_kernel<<<g1, b1>>>(x, weight);

    dcn_mma_kernel<<<256, 256, SMEM_TOTAL>>>(offset, bias, out);
}